// round 13
// baseline (speedup 1.0000x reference)
#include <cuda_runtime.h>
#include <math.h>

#define TS 512
#define BN 128
#define IND 32
#define HN 512
#define ON 8
#define PN 64

// per-CTA fx slab: [cta][t][bb][hl]  (134 MB scratch)
__device__ float g_fxp[(size_t)BN * TS * 8 * 64];

typedef unsigned long long ull;

__device__ __forceinline__ ull ffma2(ull a, ull b, ull c) {
    ull d; asm("fma.rn.f32x2 %0,%1,%2,%3;" : "=l"(d) : "l"(a), "l"(b), "l"(c)); return d;
}
__device__ __forceinline__ ull pk2(float x, float y) {
    ull d; asm("mov.b64 %0,{%1,%2};" : "=l"(d) : "f"(x), "f"(y)); return d;
}
__device__ __forceinline__ void unpk2(ull a, float& lo, float& hi) {
    asm("mov.b64 {%0,%1},%2;" : "=f"(lo), "=f"(hi) : "l"(a));
}
__device__ __forceinline__ unsigned smem_u32(const void* p) {
    unsigned a;
    asm("{ .reg .u64 t; cvta.to.shared.u64 t, %1; cvt.u32.u64 %0, t; }"
        : "=r"(a) : "l"(p));
    return a;
}

// SMEM map (dynamic):
//   [0      , 131072) wr2_s   : Wr slice, ulonglong2[8192]
//   [131072 , 163840) rdup    : [8][256] ulonglong2 (dup pairs for chain)
//   [163840 , 196608) rplain  : [2][8][512] float (exchange staging)
//   [196608 , 212992) wout_sh : Wout^T
//   [212992 , 213248) part_y
//   [213248 , 213256) mbar
// prologue scratch lives inside rdup+rplain region (overwritten later):
//   ws  at 131072 (64*33 f), lp at 139520 (64*65 f), xst at 156160 (2*264 f)
#define SM_TOTAL 213264

__global__ void __launch_bounds__(256, 1) __cluster_dims__(8, 1, 1)
snn_kernel(const float* __restrict__ x,    const float* __restrict__ Win,
           const float* __restrict__ Wout, const float* __restrict__ pin,
           const float* __restrict__ pout, const float* __restrict__ l,
           float* __restrict__ out,
           float arg_ls, float arg_lm, float arg_ld,
           float rgain, float dtc, float tref)
{
    extern __shared__ __align__(16) unsigned char smraw[];
    ulonglong2* wr2_s  = (ulonglong2*)smraw;
    ulonglong2* rdup   = (ulonglong2*)(smraw + 131072);
    float*      rplain = (float*)(smraw + 163840);
    float*      wout_sh= (float*)(smraw + 196608);
    float*      part_y = (float*)(smraw + 212992);
    const unsigned mbar = smem_u32(smraw + 213248);
    float* ws  = (float*)(smraw + 131072);
    float* lp  = (float*)(smraw + 139520);
    float* xst = (float*)(smraw + 156160);

    const int tid = threadIdx.x;
    unsigned u;
    asm("mov.u32 %0, %%cluster_ctarank;" : "=r"(u));
    const int cl   = blockIdx.x >> 3;
    const int base = cl * 8;

    const float ls  = expf(arg_ls);
    const float lm  = expf(arg_lm);
    const float ldc = expf(arg_ld);
    const float olm = 1.0f - lm;

    const int w  = tid >> 5, ln = tid & 31;
    const int hp = (w & 3) * 8 + (ln & 7);   // 0..31 local h-pair
    const int bb = (w >> 2) * 4 + (ln >> 3); // 0..7  batch
    const int hg0 = (int)u * 64 + 2 * hp;    // global h of lane-low

    float* fxslab = g_fxp + (size_t)blockIdx.x * (TS * 8 * 64);

    // ---- prologue A: stage Win slice + l*pin; init mbar ----
    if (tid == 0)
        asm volatile("mbarrier.init.shared.b64 [%0], %1;"
                     :: "r"(mbar), "r"(8u) : "memory");
    for (int i = tid; i < 64 * IND; i += 256) {
        int hl = i >> 5, ii = i & 31;
        ws[hl * 33 + ii] = Win[((int)u * 64 + hl) * IND + ii];
    }
    for (int i = tid; i < 64 * PN; i += 256) {
        int hl = i >> 6, p = i & 63;
        lp[hl * 65 + p] = __fmul_rn(l[p], pin[((int)u * 64 + hl) * PN + p]);
    }
    for (int i = tid; i < HN * ON; i += 256)
        wout_sh[i] = Wout[(i & 7) * HN + (i >> 3)];
    __syncthreads();

    // ---- prologue B: Wr slice (bit-locked sequential-p chains) ----
#pragma unroll 1
    for (int k = 0; k < 32; k++) {
        const int e   = tid + k * 256;
        const int j2  = e >> 5, hpx = e & 31;
        const int j   = 2 * j2;
        const float* l0 = lp + (2 * hpx) * 65;
        const float* l1 = l0 + 65;
        const float* p0 = pout + (size_t)j * PN;
        const float* p1 = p0 + PN;
        float w00 = 0.f, w10 = 0.f, w01 = 0.f, w11 = 0.f;
#pragma unroll
        for (int p = 0; p < PN; p++) {
            const float a0 = l0[p], a1 = l1[p];
            const float b0 = __ldg(p0 + p), b1 = __ldg(p1 + p);
            w00 = __fmaf_rn(a0, b0, w00);
            w10 = __fmaf_rn(a1, b0, w10);
            w01 = __fmaf_rn(a0, b1, w01);
            w11 = __fmaf_rn(a1, b1, w11);
        }
        wr2_s[e] = make_ulonglong2(pk2(w00, w10), pk2(w01, w11));
    }

    // ---- prologue C: fx slab (bit-locked sequential-i chains) ----
#pragma unroll 1
    for (int t0 = 0; t0 < TS; t0 += 2) {
        __syncthreads();
        {
            int i0 = tid;
            int tt = i0 >> 8, b = (i0 >> 5) & 7, ii = i0 & 31;
            xst[tt * 264 + b * 33 + ii] =
                x[((size_t)(t0 + tt) * BN + base + b) * IND + ii];
            i0 += 256;
            tt = i0 >> 8; b = (i0 >> 5) & 7; ii = i0 & 31;
            xst[tt * 264 + b * 33 + ii] =
                x[((size_t)(t0 + tt) * BN + base + b) * IND + ii];
        }
        __syncthreads();
        const float* w0 = ws + (2 * hp) * 33;
        const float* w1 = w0 + 33;
#pragma unroll
        for (int tt = 0; tt < 2; tt++) {
            const float* xv = xst + tt * 264 + bb * 33;
            float a0 = 0.f, a1 = 0.f;
#pragma unroll
            for (int i = 0; i < IND; i++) {
                const float xi = xv[i];
                a0 = __fmaf_rn(w0[i], xi, a0);
                a1 = __fmaf_rn(w1[i], xi, a1);
            }
            *(float2*)(fxslab + ((size_t)(t0 + tt) * 8 + bb) * 64 + 2 * hp) =
                make_float2(a0, a1);
        }
    }
    __syncthreads();

    // zero rplain slot 0 (r(-1) = 0)
    for (int i = tid; i < 8 * HN; i += 256) rplain[i] = 0.0f;

    // DSMEM bases in every cluster CTA
    unsigned rp_base[8], mb_base[8];
    {
        const unsigned rp_local = smem_u32(rplain);
#pragma unroll
        for (int k = 0; k < 8; k++) {
            asm("mapa.shared::cluster.u32 %0,%1,%2;"
                : "=r"(rp_base[k]) : "r"(rp_local), "r"(k));
            asm("mapa.shared::cluster.u32 %0,%1,%2;"
                : "=r"(mb_base[k]) : "r"(mbar), "r"(k));
        }
    }

    float I[2]   = {0.f, 0.f};
    float mem[2] = {0.f, 0.f};
    float s[2]   = {0.f, 0.f};
    float r[2]   = {0.f, 0.f};
    float tl[2]  = {-1.f, -1.f};

    const float2* fxp2 = (const float2*)fxslab;
    __syncthreads();
    float2 fxc = fxp2[bb * 32 + hp];

    // mbar inited + rplain zeroed cluster-wide before any arrives/pushes
    asm volatile("barrier.cluster.arrive.aligned;" ::: "memory");
    asm volatile("barrier.cluster.wait.aligned;"   ::: "memory");

#pragma unroll 1
    for (int t = 0; t < TS; t++) {
        const int sl_r = t & 1;          // staging slot holding r(t-1)
        const int sl_w = sl_r ^ 1;       // slot receiving r(t)
        const int tn = (t < TS - 1) ? t + 1 : t;
        const float2 fxn = fxp2[(size_t)tn * 256 + bb * 32 + hp];

        // dup pass: rplain[sl_r] -> rdup (pair format for the chain)
        {
            const float2* src = (const float2*)(rplain + sl_r * 4096);
#pragma unroll
            for (int i = 0; i < 8; i++) {
                const int idx = tid + i * 256;          // (bbx<<8) | j2
                const float2 v = src[idx];
                rdup[idx] = make_ulonglong2(pk2(v.x, v.x), pk2(v.y, v.y));
            }
        }
        __syncthreads();

        // ONE FFMA2 chain, sequential in j (bit-exact vs scalar chain)
        const ulonglong2* d = rdup + bb * 256;
        ull acc = 0ull;
#pragma unroll 16
        for (int j2 = 0; j2 < 256; j2++) {
            const ulonglong2 q  = wr2_s[j2 * 32 + hp];
            const ulonglong2 rr = d[j2];
            acc = ffma2(q.x, rr.x, acc);
            acc = ffma2(q.y, rr.y, acc);
        }
        float rec[2], fxv[2];
        unpk2(acc, rec[0], rec[1]);
        fxv[0] = fxc.x; fxv[1] = fxc.y;

        const float ti = __fmul_rn(dtc, (float)t);
#pragma unroll
        for (int hh = 0; hh < 2; hh++) {
            I[hh] = __fadd_rn(__fadd_rn(__fmul_rn(ls, I[hh]), fxv[hh]), rec[hh]);
            const float notref = (ti > __fadd_rn(tl[hh], tref)) ? 1.0f : 0.0f;
            const float memn = __fmul_rn(__fmul_rn(notref,
                    __fadd_rn(__fmul_rn(lm, mem[hh]), __fmul_rn(olm, I[hh]))),
                    __fsub_rn(1.0f, s[hh]));
            r[hh] = __fadd_rn(__fmul_rn(ldc, r[hh]), __fmul_rn(rgain, s[hh]));
            const float snew = (__fsub_rn(memn, 1.0f) > 0.0f) ? 1.0f : 0.0f;
            tl[hh] = __fadd_rn(tl[hh], __fmul_rn(__fsub_rn(ti, tl[hh]), snew));
            mem[hh] = memn; s[hh] = snew;
        }
        fxc = fxn;

        // push r(t) (raw float2, 8 B) into rplain[sl_w] of all 8 cluster CTAs
        {
            const ull v = pk2(r[0], r[1]);
            const unsigned off = (unsigned)(sl_w * 4096 + bb * 512 + hg0) * 4u;
#pragma unroll
            for (int k = 0; k < 8; k++)
                asm volatile("st.shared::cluster.b64 [%0], %1;"
                             :: "r"(rp_base[k] + off), "l"(v) : "memory");
        }
        __syncthreads();       // all threads' pushes issued before the arrive
        if (tid == 0) {
            asm volatile("fence.acq_rel.cluster;" ::: "memory");
#pragma unroll
            for (int k = 0; k < 8; k++)
                asm volatile("mbarrier.arrive.shared::cluster.b64 _, [%0];"
                             :: "r"(mb_base[k]) : "memory");
            // wait for all 8 arrivals (phase parity = t&1)
            unsigned done;
            asm volatile(
                "{\n\t.reg .pred p;\n\t"
                "mbarrier.try_wait.parity.acquire.cta.shared::cta.b64 p, [%1], %2;\n\t"
                "selp.b32 %0, 1, 0, p;\n\t}"
                : "=r"(done) : "r"(mbar), "r"((unsigned)(t & 1)) : "memory");
            if (!done) {
                asm volatile(
                    "{\n\t.reg .pred P1;\n\t"
                    "WL_%=:\n\t"
                    "mbarrier.try_wait.parity.acquire.cta.shared::cta.b64 P1, [%0], %1, 0x989680;\n\t"
                    "@P1 bra.uni WD_%=;\n\t"
                    "bra.uni WL_%=;\n\t"
                    "WD_%=:\n\t}"
                    :: "r"(mbar), "r"((unsigned)(t & 1)) : "memory");
            }
            asm volatile("fence.acq_rel.cluster;" ::: "memory");
        }
        __syncthreads();       // completion + acquired data visible CTA-wide

        // y for batch (base+u) from r(t) in rplain[sl_w] (same sum order)
        if (tid < 64) {
            const int o = tid & 7, seg = tid >> 3;
            const float* wq = wout_sh + (seg << 6) * 8 + o;
            const float* rr = rplain + sl_w * 4096 + (int)u * 512 + (seg << 6);
            float e0 = 0.0f, e1 = 0.0f;
#pragma unroll
            for (int hh = 0; hh < 64; hh += 2) {
                e0 = __fmaf_rn(wq[hh << 3],       rr[hh],     e0);
                e1 = __fmaf_rn(wq[(hh + 1) << 3], rr[hh + 1], e1);
            }
            part_y[tid] = e0 + e1;
        }
        __syncthreads();
        if (tid < ON) {
            const float* q = part_y + tid;
            float v = ((q[0] + q[8]) + (q[16] + q[24])) +
                      ((q[32] + q[40]) + (q[48] + q[56]));
            out[((size_t)t * BN + base + u) * ON + tid] = v;
        }
    }

    // quiesce cluster before exit (no in-flight DSMEM into exiting CTAs)
    asm volatile("barrier.cluster.arrive.aligned;" ::: "memory");
    asm volatile("barrier.cluster.wait.aligned;"   ::: "memory");
}

extern "C" void kernel_launch(void* const* d_in, const int* in_sizes, int n_in,
                              void* d_out, int out_size) {
    const float* x    = (const float*)d_in[0];
    const float* Win  = (const float*)d_in[1];
    const float* Wout = (const float*)d_in[2];
    const float* pin  = (const float*)d_in[3];
    const float* pout = (const float*)d_in[4];
    const float* l    = (const float*)d_in[5];
    float* out = (float*)d_out;

    const float arg_ls = (float)(-0.002 / 0.01);
    const float arg_lm = (float)(-0.002 / 0.02);
    const float arg_ld = (float)(-0.002 / 0.03);
    const float rgain  = (float)(0.002 / 0.03);
    const float dtc    = (float)0.002;
    const float tref   = (float)(5.0 * 0.002);

    cudaFuncSetAttribute(snn_kernel, cudaFuncAttributeMaxDynamicSharedMemorySize,
                         SM_TOTAL);

    snn_kernel<<<BN, 256, SM_TOTAL>>>(x, Win, Wout, pin, pout, l, out,
                                      arg_ls, arg_lm, arg_ld, rgain, dtc, tref);
}

// round 15
// speedup vs baseline: 2.1805x; 2.1805x over previous
#include <cuda_runtime.h>
#include <math.h>

#define TS 512
#define BN 128
#define IND 32
#define HN 512
#define ON 8
#define PN 64

// FX[t,b,h] = sum_i Win[h,i]*x[t,b,i]  (134 MB scratch)
__device__ float g_fx[(size_t)TS * BN * HN];
// Wr in h-pair/j-pair interleaved layout: ulonglong2 at [j2*256 + hp] =
// ( W[h0][j], W[h1][j] | W[h0][j+1], W[h1][j+1] ),  h0=2*hp, j=2*j2.
__device__ float g_wr2[(size_t)HN * HN];

typedef unsigned long long ull;

__device__ __forceinline__ ull ffma2(ull a, ull b, ull c) {
    ull d; asm("fma.rn.f32x2 %0,%1,%2,%3;" : "=l"(d) : "l"(a), "l"(b), "l"(c)); return d;
}
__device__ __forceinline__ ull pk2(float x, float y) {
    ull d; asm("mov.b64 %0,{%1,%2};" : "=l"(d) : "f"(x), "f"(y)); return d;
}
__device__ __forceinline__ void unpk2(ull a, float& lo, float& hi) {
    asm("mov.b64 {%0,%1},%2;" : "=f"(lo), "=f"(hi) : "l"(a));
}

// ---------------------------------------------------------------------------
// Kernel 1: FX = x @ Win^T, strict sequential-k FMA chain (bit-locked).
// ---------------------------------------------------------------------------
__global__ void __launch_bounds__(512, 1)
fx_kernel(const float* __restrict__ x, const float* __restrict__ Win) {
    __shared__ __align__(16) float xs[64 * IND];
    const int tid = threadIdx.x;

    float w[32];
    const float4* wr4 = (const float4*)(Win + tid * IND);
#pragma unroll
    for (int k = 0; k < 8; k++) {
        float4 f = wr4[k];
        w[4 * k + 0] = f.x; w[4 * k + 1] = f.y;
        w[4 * k + 2] = f.z; w[4 * k + 3] = f.w;
    }

    const int pair0 = blockIdx.x * 64;
    ((float4*)xs)[tid] = ((const float4*)(x + (size_t)pair0 * IND))[tid];
    __syncthreads();

    float* outp = g_fx + (size_t)pair0 * HN + tid;
#pragma unroll 4
    for (int k = 0; k < 64; k++) {
        const float* xk = xs + k * IND;
        float acc = 0.0f;
#pragma unroll
        for (int i = 0; i < IND; i++) acc = __fmaf_rn(w[i], xk[i], acc);
        outp[(size_t)k * HN] = acc;
    }
}

// ---------------------------------------------------------------------------
// Kernel 2: Wr[h][j] via sequential-p chain (bit-locked), h/j-pair interleaved.
// ---------------------------------------------------------------------------
__global__ void __launch_bounds__(512, 1)
wr_kernel(const float* __restrict__ pin, const float* __restrict__ pout,
          const float* __restrict__ l) {
    __shared__ float lp[PN];
    const int h = blockIdx.x;
    const int j = threadIdx.x;
    if (j < PN) lp[j] = __fmul_rn(l[j], pin[h * PN + j]);
    __syncthreads();

    const float* pr = pout + j * PN;
    float acc = 0.0f;
#pragma unroll
    for (int p = 0; p < PN; p++) acc = __fmaf_rn(lp[p], pr[p], acc);

    const size_t q4 = (size_t)(j >> 1) * 256 + (h >> 1);
    g_wr2[q4 * 4 + (h & 1) + 2 * (j & 1)] = acc;
}

// ---------------------------------------------------------------------------
// Kernel 3: scan. One CTA = one batch (CTA-LOCAL, zero cross-CTA sync).
// 256 threads, thread = h-pair; one FFMA2 chain of 512 (bit-exact order,
// proven). Wr streamed from L2 in pair layout; r kept as duplicated pairs
// in a parity-double-buffered SMEM array, published by the owner thread.
// ---------------------------------------------------------------------------
__global__ void __launch_bounds__(256, 1)
snn_kernel(const float* __restrict__ Wout, float* __restrict__ out,
           float arg_ls, float arg_lm, float arg_ld,
           float rgain, float dtc, float tref)
{
    __shared__ __align__(16) ulonglong2 rdup[2][256];   // [parity][j2] dup pairs
    __shared__ __align__(16) float woutT_sh[HN * ON];   // Wout^T[h][o]
    __shared__ float part_y[64];

    const int tid = threadIdx.x;
    const int b   = blockIdx.x;
    const int hp  = tid;                 // h-pair 0..255 (h0=2hp, h1=2hp+1)

    const float ls  = expf(arg_ls);
    const float lm  = expf(arg_lm);
    const float ldc = expf(arg_ld);
    const float olm = 1.0f - lm;

    for (int i = tid; i < HN * ON; i += 256)
        woutT_sh[i] = Wout[(i & 7) * HN + (i >> 3)];
    // zero parity-0 r buffer (r(-1) = 0)
    rdup[0][tid] = make_ulonglong2(0ull, 0ull);

    // neuron state for (h0, h1)
    float I[2]   = {0.f, 0.f};
    float mem[2] = {0.f, 0.f};
    float s[2]   = {0.f, 0.f};
    float r[2]   = {0.f, 0.f};
    float tl[2]  = {-1.f, -1.f};

    const float2* fxp = (const float2*)(g_fx + (size_t)b * HN + 2 * hp);
    float2 fxc = fxp[0];

    const ulonglong2* wp = (const ulonglong2*)g_wr2;   // [j2*256 + hp]

    __syncthreads();

#pragma unroll 1
    for (int t = 0; t < TS; t++) {
        const int par = t & 1, pn = par ^ 1;
        const int tn = (t < TS - 1) ? t + 1 : t;
        const float2 fxn = fxp[(size_t)tn * (BN * HN / 2)];   // prefetch

        // ONE FFMA2 chain, sequential in j (bit-exact, proven R7..R13)
        const ulonglong2* d = &rdup[par][0];
        ull acc = 0ull;
#pragma unroll 8
        for (int j2 = 0; j2 < 256; j2++) {
            const ulonglong2 q  = wp[(size_t)j2 * 256 + hp];  // LDG.128 coalesced
            const ulonglong2 rr = d[j2];                      // LDS.128 broadcast
            acc = ffma2(q.x, rr.x, acc);
            acc = ffma2(q.y, rr.y, acc);
        }
        float rec[2], fxv[2];
        unpk2(acc, rec[0], rec[1]);
        fxv[0] = fxc.x; fxv[1] = fxc.y;

        const float ti = __fmul_rn(dtc, (float)t);
#pragma unroll
        for (int hh = 0; hh < 2; hh++) {
            I[hh] = __fadd_rn(__fadd_rn(__fmul_rn(ls, I[hh]), fxv[hh]), rec[hh]);
            const float notref = (ti > __fadd_rn(tl[hh], tref)) ? 1.0f : 0.0f;
            const float memn = __fmul_rn(__fmul_rn(notref,
                    __fadd_rn(__fmul_rn(lm, mem[hh]), __fmul_rn(olm, I[hh]))),
                    __fsub_rn(1.0f, s[hh]));
            r[hh] = __fadd_rn(__fmul_rn(ldc, r[hh]), __fmul_rn(rgain, s[hh]));
            const float snew = (__fsub_rn(memn, 1.0f) > 0.0f) ? 1.0f : 0.0f;
            tl[hh] = __fadd_rn(tl[hh], __fmul_rn(__fsub_rn(ti, tl[hh]), snew));
            mem[hh] = memn; s[hh] = snew;
        }
        fxc = fxn;

        // publish r(t) as dup pairs into parity pn: one STS.128, conflict-free
        rdup[pn][hp] = make_ulonglong2(pk2(r[0], r[0]), pk2(r[1], r[1]));
        __syncthreads();   // r(t) visible; chain reads of rdup[par] complete

        // y partials from r(t). Segment seg covers h in [seg*64, seg*64+64)
        // = j2 in [seg*32, ...): base index seg<<5 (FIXED from seg<<3).
        // float offset of r(h) in this layout = 2h, so rr[2*hh] below reads
        // exactly r(seg*64+hh) — same bits, same sum order as R6..R13.
        if (tid < 64) {
            const int o = tid & 7, seg = tid >> 3;
            const float* wq = woutT_sh + (seg << 6) * 8 + o;
            const float* rr = (const float*)&rdup[pn][seg << 5];
            float e0 = 0.0f, e1 = 0.0f;
#pragma unroll
            for (int hh = 0; hh < 64; hh += 2) {
                e0 = __fmaf_rn(wq[hh << 3],       rr[hh * 2],       e0);
                e1 = __fmaf_rn(wq[(hh + 1) << 3], rr[(hh + 1) * 2], e1);
            }
            part_y[tid] = e0 + e1;
        }
        __syncthreads();   // part_y visible
        if (tid < ON) {
            const float* q = part_y + tid;
            float v = ((q[0] + q[8]) + (q[16] + q[24])) +
                      ((q[32] + q[40]) + (q[48] + q[56]));
            out[((size_t)t * BN + b) * ON + tid] = v;
        }
        // next step's publish targets rdup[par] (disjoint from y's rdup[pn]
        // reads, which complete before the publish-side __syncthreads) — safe.
    }
}

extern "C" void kernel_launch(void* const* d_in, const int* in_sizes, int n_in,
                              void* d_out, int out_size) {
    const float* x    = (const float*)d_in[0];
    const float* Win  = (const float*)d_in[1];
    const float* Wout = (const float*)d_in[2];
    const float* pin  = (const float*)d_in[3];
    const float* pout = (const float*)d_in[4];
    const float* l    = (const float*)d_in[5];
    float* out = (float*)d_out;

    const float arg_ls = (float)(-0.002 / 0.01);
    const float arg_lm = (float)(-0.002 / 0.02);
    const float arg_ld = (float)(-0.002 / 0.03);
    const float rgain  = (float)(0.002 / 0.03);
    const float dtc    = (float)0.002;
    const float tref   = (float)(5.0 * 0.002);

    fx_kernel<<<(TS * BN) / 64, 512>>>(x, Win);
    wr_kernel<<<HN, 512>>>(pin, pout, l);
    snn_kernel<<<BN, 256>>>(Wout, out, arg_ls, arg_lm, arg_ld, rgain, dtc, tref);
}